// round 9
// baseline (speedup 1.0000x reference)
#include <cuda_runtime.h>
#include <cuda_bf16.h>
#include <math.h>
#include <stdint.h>

#define NTOK 16384
#define DM   1024
#define NE   4
#define DH   2048

// ------------------------- device scratch ------------------------------------
__device__ int   g_count[NE];
__device__ int   g_tok [NE * NTOK];
__device__ int   g_eid [NTOK * 2];
__device__ int   g_slot[NTOK * 2];
__device__ float g_wt  [NTOK * 2];

__device__ __nv_bfloat16 g_xh [(size_t)NTOK * DM];
__device__ __nv_bfloat16 g_xl [(size_t)NTOK * DM];
__device__ __nv_bfloat16 g_w1h[(size_t)NE * DH * DM];
__device__ __nv_bfloat16 g_w1l[(size_t)NE * DH * DM];
__device__ __nv_bfloat16 g_w2h[(size_t)NE * DM * DH];
__device__ __nv_bfloat16 g_w2l[(size_t)NE * DM * DH];
__device__ __nv_bfloat16 g_Hh [(size_t)NE * NTOK * DH];
__device__ __nv_bfloat16 g_Hl [(size_t)NE * NTOK * DH];
__device__ float         g_Z  [(size_t)NE * NTOK * DM];

// ------------------------- PTX helpers (no 'a' features) ----------------------
__device__ __forceinline__ uint32_t smem_u32(const void* p) {
    uint32_t a;
    asm("{ .reg .u64 t; cvta.to.shared.u64 t, %1; cvt.u32.u64 %0, t; }" : "=r"(a) : "l"(p));
    return a;
}
__device__ __forceinline__ void cpa16(uint32_t dst, const void* src) {
    asm volatile("cp.async.cg.shared.global [%0], [%1], 16;" :: "r"(dst), "l"(src));
}
__device__ __forceinline__ void cpa_commit() {
    asm volatile("cp.async.commit_group;" ::: "memory");
}
template <int N> __device__ __forceinline__ void cpa_wait() {
    asm volatile("cp.async.wait_group %0;" :: "n"(N) : "memory");
}
__device__ __forceinline__ void ldsm4(uint32_t* r, uint32_t addr) {
    asm volatile("ldmatrix.sync.aligned.m8n8.x4.shared.b16 {%0,%1,%2,%3}, [%4];"
                 : "=r"(r[0]), "=r"(r[1]), "=r"(r[2]), "=r"(r[3]) : "r"(addr));
}
__device__ __forceinline__ void mma_bf16(float* c, const uint32_t* a,
                                         uint32_t b0, uint32_t b1) {
    asm volatile(
        "mma.sync.aligned.m16n8k16.row.col.f32.bf16.bf16.f32 "
        "{%0,%1,%2,%3}, {%4,%5,%6,%7}, {%8,%9}, {%0,%1,%2,%3};"
        : "+f"(c[0]), "+f"(c[1]), "+f"(c[2]), "+f"(c[3])
        : "r"(a[0]), "r"(a[1]), "r"(a[2]), "r"(a[3]), "r"(b0), "r"(b1));
}

// ------------------------- small kernels -------------------------------------
__global__ void reset_kernel() {
    if (threadIdx.x < NE) g_count[threadIdx.x] = 0;
}

__global__ void gate_kernel(const float* __restrict__ x,
                            const float* __restrict__ gw) {
    int t = blockIdx.x, tid = threadIdx.x, w = tid >> 5, lane = tid & 31;
    const float4* xr = (const float4*)(x + (size_t)t * DM);
    const float4* gr = (const float4*)(gw + (size_t)w * DM);
    float s = 0.f;
    for (int k = lane; k < DM / 4; k += 32) {
        float4 a = xr[k], b = gr[k];
        s += a.x * b.x + a.y * b.y + a.z * b.z + a.w * b.w;
    }
    #pragma unroll
    for (int o = 16; o; o >>= 1) s += __shfl_xor_sync(0xffffffffu, s, o);
    __shared__ float sc[NE];
    if (lane == 0) sc[w] = s;
    __syncthreads();
    if (tid == 0) {
        int i0 = 0;
        #pragma unroll
        for (int i = 1; i < NE; i++) if (sc[i] > sc[i0]) i0 = i;
        int i1 = -1;
        #pragma unroll
        for (int i = 0; i < NE; i++) {
            if (i == i0) continue;
            if (i1 < 0 || sc[i] > sc[i1]) i1 = i;
        }
        float m = fmaxf(sc[i0], sc[i1]);
        float e0 = expf(sc[i0] - m), e1 = expf(sc[i1] - m);
        float inv = 1.f / (e0 + e1);
        int s0 = atomicAdd(&g_count[i0], 1);
        int s1 = atomicAdd(&g_count[i1], 1);
        g_eid [t * 2] = i0;  g_eid [t * 2 + 1] = i1;
        g_slot[t * 2] = s0;  g_slot[t * 2 + 1] = s1;
        g_wt  [t * 2] = e0 * inv;
        g_wt  [t * 2 + 1] = e1 * inv;
        g_tok[i0 * NTOK + s0] = t;
        g_tok[i1 * NTOK + s1] = t;
    }
}

// fp32 -> bf16 hi/lo split, 8 elems/thread
__global__ void split_kernel(const float* __restrict__ src,
                             __nv_bfloat16* __restrict__ hi,
                             __nv_bfloat16* __restrict__ lo, int n8) {
    int i = blockIdx.x * blockDim.x + threadIdx.x;
    if (i >= n8) return;
    float4 v0 = ((const float4*)src)[i * 2];
    float4 v1 = ((const float4*)src)[i * 2 + 1];
    float vv[8] = {v0.x, v0.y, v0.z, v0.w, v1.x, v1.y, v1.z, v1.w};
    alignas(16) __nv_bfloat16 h[8], l[8];
    #pragma unroll
    for (int j = 0; j < 8; j++) {
        h[j] = __float2bfloat16_rn(vv[j]);
        l[j] = __float2bfloat16_rn(vv[j] - __bfloat162float(h[j]));
    }
    ((uint4*)hi)[i] = *(uint4*)h;
    ((uint4*)lo)[i] = *(uint4*)l;
}

// ------------------------- HMMA GEMM ------------------------------------------
// C[m,n] = sum_k A[m,k]*B[n,k]; bf16 hi/lo split: AhBh + AlBh + AhBl.
// CTA 128x256, BK=64, 8 warps (2m x 4n), warp tile 64x64.
// 2-stage ring, 128B rows, SW128-style chunk swizzle (chunk ^= row&7).
// Stage layout (rows of 128B): [0,128)=A hi, [128,256)=A lo,
//                              [256,512)=B hi, [512,768)=B lo.
#define BM 128
#define BN 256
#define BK 64
#define STG    98304           // 768 rows * 128 B
#define SMEM_TOTAL (2 * STG)   // 196608

template <int PHASE>
__global__ void __launch_bounds__(256, 1)
gemm_mma(const float* __restrict__ bias) {
    constexpr int K = (PHASE == 1) ? DM : DH;
    constexpr int N = (PHASE == 1) ? DH : DM;
    constexpr int S = K / BK;

    const int e   = blockIdx.z;
    const int cnt = g_count[e];
    const int m0  = blockIdx.y * BM;
    if (m0 >= cnt) return;
    const int n0  = blockIdx.x * BN;

    extern __shared__ char dsm[];
    const uint32_t BUF = smem_u32(dsm);

    const int tid  = threadIdx.x;
    const int lane = tid & 31;
    const int wid  = tid >> 5;        // 0..7
    const int wm   = wid >> 2;        // 0..1  (m base wm*64)
    const int wn   = wid & 3;         // 0..3  (n base wn*64)

    // -------- cp.async: thread handles smem rows tid, tid+256, tid+512 -------
    // row tid:    A (part hi if tid<128 else lo), token/slot row (tid&127)
    // row tid+256: B hi, n = tid
    // row tid+512: B lo, n = tid
    const int arow = tid & 127, apart = tid >> 7;
    const __nv_bfloat16* gp0;
    if (PHASE == 1) {
        int row = m0 + arow;
        int tok = (row < cnt) ? g_tok[e * NTOK + row] : 0;
        gp0 = (apart ? g_xl : g_xh) + (size_t)tok * DM;
    } else {
        size_t rr = (size_t)e * NTOK + m0 + arow;
        gp0 = (apart ? g_Hl : g_Hh) + rr * DH;
    }
    const __nv_bfloat16* Wh = (PHASE == 1) ? g_w1h : g_w2h;
    const __nv_bfloat16* Wl = (PHASE == 1) ? g_w1l : g_w2l;
    const __nv_bfloat16* gp1 = Wh + ((size_t)e * N + n0 + tid) * K;
    const __nv_bfloat16* gp2 = Wl + ((size_t)e * N + n0 + tid) * K;

    const uint32_t rsw  = (uint32_t)(tid & 7);
    const uint32_t d0   = (uint32_t)tid * 128;
    const uint32_t d1   = d0 + 256 * 128;
    const uint32_t d2   = d0 + 512 * 128;

    auto load_stage = [&](int s) {
        const int kb = s * BK;
        const uint32_t sb = BUF + (uint32_t)(s & 1) * STG;
        #pragma unroll
        for (uint32_t c = 0; c < 8; c++) {
            const uint32_t co = (c ^ rsw) << 4;
            cpa16(sb + d0 + co, gp0 + kb + c * 8);
            cpa16(sb + d1 + co, gp1 + kb + c * 8);
            cpa16(sb + d2 + co, gp2 + kb + c * 8);
        }
        cpa_commit();
    };

    // -------- ldsm per-lane constants --------
    const uint32_t rl   = (uint32_t)((((lane >> 3) & 1) * 8) + (lane & 7)); // 0..15
    const uint32_t jsel = (uint32_t)((lane >> 4) & 1);
    const uint32_t rb   = rl * 128;
    uint32_t sj[4];
    #pragma unroll
    for (uint32_t kk = 0; kk < 4; kk++)
        sj[kk] = ((2 * kk + jsel) ^ (rl & 7)) << 4;

    float acc[4][8][4];
    #pragma unroll
    for (int i = 0; i < 4; i++)
        #pragma unroll
        for (int j = 0; j < 8; j++)
            #pragma unroll
            for (int q = 0; q < 4; q++) acc[i][j][q] = 0.f;

    load_stage(0);
    load_stage(1);

    for (int s = 0; s < S; s++) {
        if (s >= S - 2) cpa_wait<0>(); else cpa_wait<1>();
        __syncthreads();

        const uint32_t sb  = BUF + (uint32_t)(s & 1) * STG;
        const uint32_t aB  = sb + (uint32_t)(wm * 8192) + rb;          // A hi base
        const uint32_t bB  = sb + 32768u + (uint32_t)(wn * 8192) + rb; // B hi base

        #pragma unroll
        for (uint32_t kk = 0; kk < 4; kk++) {
            const uint32_t cx = sj[kk];
            uint32_t ah[4][4], al[4][4], bb[4][4];
            #pragma unroll
            for (int mt = 0; mt < 4; mt++) {
                ldsm4(ah[mt], aB + mt * 2048 + cx);
                ldsm4(al[mt], aB + 16384 + mt * 2048 + cx);
            }
            #pragma unroll
            for (int nb = 0; nb < 4; nb++)
                ldsm4(bb[nb], bB + nb * 2048 + cx);               // B hi
            #pragma unroll
            for (int mt = 0; mt < 4; mt++)
                #pragma unroll
                for (int nb = 0; nb < 4; nb++) {
                    mma_bf16(acc[mt][2 * nb],     ah[mt], bb[nb][0], bb[nb][2]);
                    mma_bf16(acc[mt][2 * nb + 1], ah[mt], bb[nb][1], bb[nb][3]);
                }
            #pragma unroll
            for (int mt = 0; mt < 4; mt++)
                #pragma unroll
                for (int nb = 0; nb < 4; nb++) {
                    mma_bf16(acc[mt][2 * nb],     al[mt], bb[nb][0], bb[nb][2]);
                    mma_bf16(acc[mt][2 * nb + 1], al[mt], bb[nb][1], bb[nb][3]);
                }
            #pragma unroll
            for (int nb = 0; nb < 4; nb++)
                ldsm4(bb[nb], bB + 32768 + nb * 2048 + cx);       // B lo
            #pragma unroll
            for (int mt = 0; mt < 4; mt++)
                #pragma unroll
                for (int nb = 0; nb < 4; nb++) {
                    mma_bf16(acc[mt][2 * nb],     ah[mt], bb[nb][0], bb[nb][2]);
                    mma_bf16(acc[mt][2 * nb + 1], ah[mt], bb[nb][1], bb[nb][3]);
                }
        }

        if (s + 2 < S) {
            __syncthreads();        // everyone done reading buf (s&1)
            load_stage(s + 2);
        }
    }

    // -------- epilogue --------
    const int grp = lane >> 2, qid = lane & 3;
    float bc[8][2];
    #pragma unroll
    for (int nt = 0; nt < 8; nt++) {
        int col = n0 + wn * 64 + nt * 8 + qid * 2;
        bc[nt][0] = __ldg(bias + e * N + col);
        bc[nt][1] = __ldg(bias + e * N + col + 1);
    }
    #pragma unroll
    for (int mt = 0; mt < 4; mt++) {
        #pragma unroll
        for (int h = 0; h < 2; h++) {
            int r = m0 + wm * 64 + mt * 16 + grp + h * 8;
            if (r >= cnt) continue;
            #pragma unroll
            for (int nt = 0; nt < 8; nt++) {
                int col = n0 + wn * 64 + nt * 8 + qid * 2;
                float v0 = acc[mt][nt][h * 2 + 0] + bc[nt][0];
                float v1 = acc[mt][nt][h * 2 + 1] + bc[nt][1];
                if (PHASE == 1) {
                    v0 = 0.5f * v0 * (1.f + erff(v0 * 0.70710678118654752f));
                    v1 = 0.5f * v1 * (1.f + erff(v1 * 0.70710678118654752f));
                    __nv_bfloat162 hv, lv;
                    hv.x = __float2bfloat16_rn(v0);
                    hv.y = __float2bfloat16_rn(v1);
                    lv.x = __float2bfloat16_rn(v0 - __bfloat162float(hv.x));
                    lv.y = __float2bfloat16_rn(v1 - __bfloat162float(hv.y));
                    size_t off = ((size_t)e * NTOK + r) * DH + col;
                    *(__nv_bfloat162*)(g_Hh + off) = hv;
                    *(__nv_bfloat162*)(g_Hl + off) = lv;
                } else {
                    float2 o = {v0, v1};
                    *(float2*)(g_Z + ((size_t)e * NTOK + r) * DM + col) = o;
                }
            }
        }
    }
}

// ------------------------- combine -------------------------------------------
__global__ void combine_kernel(const float* __restrict__ x,
                               const float* __restrict__ gamma,
                               const float* __restrict__ beta,
                               float* __restrict__ out) {
    const int t = blockIdx.x, tid = threadIdx.x;
    __shared__ float ssum[8], ssq[8];
    const float4 xv = *(const float4*)(x + (size_t)t * DM + tid * 4);
    float acc[4] = {0.f, 0.f, 0.f, 0.f};
    #pragma unroll
    for (int p = 0; p < 2; p++) {
        int e = g_eid[t * 2 + p], s = g_slot[t * 2 + p];
        float wgt = g_wt[t * 2 + p];
        const float4 zv = *(const float4*)(g_Z + ((size_t)e * NTOK + s) * DM + tid * 4);
        float z[4] = {xv.x + zv.x, xv.y + zv.y, xv.z + zv.z, xv.w + zv.w};
        float sum = 0.f, sq = 0.f;
        #pragma unroll
        for (int i = 0; i < 4; i++) { sum += z[i]; sq += z[i] * z[i]; }
        #pragma unroll
        for (int o = 16; o; o >>= 1) {
            sum += __shfl_xor_sync(0xffffffffu, sum, o);
            sq  += __shfl_xor_sync(0xffffffffu, sq,  o);
        }
        int w = tid >> 5, lane = tid & 31;
        if (lane == 0) { ssum[w] = sum; ssq[w] = sq; }
        __syncthreads();
        float tsum = 0.f, tsq = 0.f;
        #pragma unroll
        for (int i = 0; i < 8; i++) { tsum += ssum[i]; tsq += ssq[i]; }
        __syncthreads();
        float mu = tsum * (1.f / DM);
        float var = tsq * (1.f / DM) - mu * mu;
        float rstd = rsqrtf(var + 1e-6f);
        const float4 gv = *(const float4*)(gamma + (size_t)e * DM + tid * 4);
        const float4 bv = *(const float4*)(beta  + (size_t)e * DM + tid * 4);
        const float g4[4] = {gv.x, gv.y, gv.z, gv.w};
        const float b4[4] = {bv.x, bv.y, bv.z, bv.w};
        #pragma unroll
        for (int i = 0; i < 4; i++)
            acc[i] += wgt * ((z[i] - mu) * rstd * g4[i] + b4[i]);
    }
    float4 o4 = {acc[0], acc[1], acc[2], acc[3]};
    *(float4*)(out + (size_t)t * DM + tid * 4) = o4;
}

// ------------------------- launch --------------------------------------------
extern "C" void kernel_launch(void* const* d_in, const int* in_sizes, int n_in,
                              void* d_out, int out_size) {
    const float* x     = (const float*)d_in[0];
    const float* gw    = (const float*)d_in[1];
    const float* w1    = (const float*)d_in[2];
    const float* b1    = (const float*)d_in[3];
    const float* w2    = (const float*)d_in[4];
    const float* b2    = (const float*)d_in[5];
    const float* gamma = (const float*)d_in[6];
    const float* beta  = (const float*)d_in[7];
    float* out = (float*)d_out;

    cudaFuncSetAttribute(gemm_mma<1>, cudaFuncAttributeMaxDynamicSharedMemorySize, SMEM_TOTAL);
    cudaFuncSetAttribute(gemm_mma<2>, cudaFuncAttributeMaxDynamicSharedMemorySize, SMEM_TOTAL);

    void *pxh, *pxl, *pw1h, *pw1l, *pw2h, *pw2l;
    cudaGetSymbolAddress(&pxh,  g_xh);
    cudaGetSymbolAddress(&pxl,  g_xl);
    cudaGetSymbolAddress(&pw1h, g_w1h);
    cudaGetSymbolAddress(&pw1l, g_w1l);
    cudaGetSymbolAddress(&pw2h, g_w2h);
    cudaGetSymbolAddress(&pw2l, g_w2l);

    reset_kernel<<<1, 32>>>();
    gate_kernel<<<NTOK, 128>>>(x, gw);

    {
        int n8 = NTOK * DM / 8;
        split_kernel<<<(n8 + 255) / 256, 256>>>(x, (__nv_bfloat16*)pxh, (__nv_bfloat16*)pxl, n8);
    }
    {
        int n8 = NE * DH * DM / 8;
        split_kernel<<<(n8 + 255) / 256, 256>>>(w1, (__nv_bfloat16*)pw1h, (__nv_bfloat16*)pw1l, n8);
        split_kernel<<<(n8 + 255) / 256, 256>>>(w2, (__nv_bfloat16*)pw2h, (__nv_bfloat16*)pw2l, n8);
    }

    dim3 g1(DH / BN, NTOK / BM, NE);
    gemm_mma<1><<<g1, 256, SMEM_TOTAL>>>(b1);

    dim3 g2(DM / BN, NTOK / BM, NE);
    gemm_mma<2><<<g2, 256, SMEM_TOTAL>>>(b2);

    combine_kernel<<<NTOK, 256>>>(x, gamma, beta, out);
}

// round 12
// speedup vs baseline: 1.4562x; 1.4562x over previous
#include <cuda_runtime.h>
#include <cuda_bf16.h>
#include <math.h>
#include <stdint.h>

#define NTOK 16384
#define DM   1024
#define NE   4
#define DH   2048

// ------------------------- device scratch ------------------------------------
__device__ int   g_count[NE];
__device__ int   g_tok [NE * NTOK];
__device__ int   g_eid [NTOK * 2];
__device__ int   g_slot[NTOK * 2];
__device__ float g_wt  [NTOK * 2];
__device__ float g_H[(size_t)NE * NTOK * DH];   // gelu(xW1^T+b1), slot order (fp32)
__device__ float g_Z[(size_t)NE * NTOK * DM];   // HW2^T+b2, slot order

// ------------------------- PTX helpers (sm_80-class only) ---------------------
__device__ __forceinline__ uint32_t smem_u32(const void* p) {
    uint32_t a;
    asm("{ .reg .u64 t; cvta.to.shared.u64 t, %1; cvt.u32.u64 %0, t; }" : "=r"(a) : "l"(p));
    return a;
}
__device__ __forceinline__ void cpa16(uint32_t dst, const void* src) {
    asm volatile("cp.async.cg.shared.global [%0], [%1], 16;" :: "r"(dst), "l"(src));
}
__device__ __forceinline__ void cpa_commit() {
    asm volatile("cp.async.commit_group;" ::: "memory");
}
template <int N> __device__ __forceinline__ void cpa_wait() {
    asm volatile("cp.async.wait_group %0;" :: "n"(N) : "memory");
}
__device__ __forceinline__ void ldsm4(uint32_t* r, uint32_t addr) {
    asm volatile("ldmatrix.sync.aligned.m8n8.x4.shared.b16 {%0,%1,%2,%3}, [%4];"
                 : "=r"(r[0]), "=r"(r[1]), "=r"(r[2]), "=r"(r[3]) : "r"(addr));
}
__device__ __forceinline__ uint32_t f2tf32(uint32_t bits) {
    uint32_t o;
    float f = __uint_as_float(bits);
    asm("cvt.rna.tf32.f32 %0, %1;" : "=r"(o) : "f"(f));
    return o;
}
__device__ __forceinline__ void mma_tf32(float* c, const uint32_t* a,
                                         uint32_t b0, uint32_t b1) {
    asm volatile(
        "mma.sync.aligned.m16n8k8.row.col.f32.tf32.tf32.f32 "
        "{%0,%1,%2,%3}, {%4,%5,%6,%7}, {%8,%9}, {%0,%1,%2,%3};"
        : "+f"(c[0]), "+f"(c[1]), "+f"(c[2]), "+f"(c[3])
        : "r"(a[0]), "r"(a[1]), "r"(a[2]), "r"(a[3]), "r"(b0), "r"(b1));
}

// ------------------------- small kernels -------------------------------------
__global__ void reset_kernel() {
    if (threadIdx.x < NE) g_count[threadIdx.x] = 0;
}

__global__ void gate_kernel(const float* __restrict__ x,
                            const float* __restrict__ gw) {
    int t = blockIdx.x, tid = threadIdx.x, w = tid >> 5, lane = tid & 31;
    const float4* xr = (const float4*)(x + (size_t)t * DM);
    const float4* gr = (const float4*)(gw + (size_t)w * DM);
    float s = 0.f;
    for (int k = lane; k < DM / 4; k += 32) {
        float4 a = xr[k], b = gr[k];
        s += a.x * b.x + a.y * b.y + a.z * b.z + a.w * b.w;
    }
    #pragma unroll
    for (int o = 16; o; o >>= 1) s += __shfl_xor_sync(0xffffffffu, s, o);
    __shared__ float sc[NE];
    if (lane == 0) sc[w] = s;
    __syncthreads();
    if (tid == 0) {
        int i0 = 0;
        #pragma unroll
        for (int i = 1; i < NE; i++) if (sc[i] > sc[i0]) i0 = i;
        int i1 = -1;
        #pragma unroll
        for (int i = 0; i < NE; i++) {
            if (i == i0) continue;
            if (i1 < 0 || sc[i] > sc[i1]) i1 = i;
        }
        float m = fmaxf(sc[i0], sc[i1]);
        float e0 = expf(sc[i0] - m), e1 = expf(sc[i1] - m);
        float inv = 1.f / (e0 + e1);
        int s0 = atomicAdd(&g_count[i0], 1);
        int s1 = atomicAdd(&g_count[i1], 1);
        g_eid [t * 2] = i0;  g_eid [t * 2 + 1] = i1;
        g_slot[t * 2] = s0;  g_slot[t * 2 + 1] = s1;
        g_wt  [t * 2] = e0 * inv;
        g_wt  [t * 2 + 1] = e1 * inv;
        g_tok[i0 * NTOK + s0] = t;
        g_tok[i1 * NTOK + s1] = t;
    }
}

// ------------------------- tf32 HMMA GEMM ------------------------------------
// C[m,n] = sum_k A[m,k]*B[n,k], single-pass tf32 (inputs cvt.rna'd in-register).
// CTA 128x256, BK=32 fp32 (128B rows), 8 warps (2m x 4n), warp tile 64x64.
// 4-stage cp.async ring; XOR chunk swizzle (chunk ^= row&7) — conflict-free ldsm.
// Stage: A = 128 rows @ 0, B = 256 rows @ 16384; stage = 49152 B.
#define BM 128
#define BN 256
#define BK 32
#define STG 49152
#define SMEM_TOTAL (4 * STG)   // 196608

template <int PHASE>
__global__ void __launch_bounds__(256, 1)
gemm_tf32(const float* __restrict__ x_in,
          const float* __restrict__ W,
          const float* __restrict__ bias) {
    constexpr int K = (PHASE == 1) ? DM : DH;
    constexpr int N = (PHASE == 1) ? DH : DM;
    constexpr int S = K / BK;

    const int e   = blockIdx.z;
    const int cnt = g_count[e];
    const int m0  = blockIdx.y * BM;
    if (m0 >= cnt) return;
    const int n0  = blockIdx.x * BN;

    extern __shared__ char dsm[];
    const uint32_t BUF = smem_u32(dsm);

    const int tid  = threadIdx.x;
    const int lane = tid & 31;
    const int wid  = tid >> 5;        // 0..7
    const int wm   = wid >> 2;        // 0..1
    const int wn   = wid & 3;         // 0..3

    // -------- cp.async mapping: 8 threads per 128B row slice, coalesced -------
    // group g = tid>>3 (0..31), chunk = tid&7 (16B = 4 fp32)
    const int grpi  = tid >> 3;
    const int chnk  = tid & 7;
    const uint32_t pchunk = (uint32_t)((chnk ^ (grpi & 7)) << 4);   // physical 16B
    const int csrc = chnk * 4;                                       // fp32 offset

    // A rows: row = grpi + 32p, p = 0..3
    const float* arow[4];
    #pragma unroll
    for (int p = 0; p < 4; p++) {
        int r = grpi + 32 * p;
        if (PHASE == 1) {
            int row = m0 + r;
            int tok = (row < cnt) ? g_tok[e * NTOK + row] : 0;
            arow[p] = x_in + (size_t)tok * DM;
        } else {
            arow[p] = g_H + ((size_t)e * NTOK + m0 + r) * DH;
        }
    }
    // B rows: row = grpi + 32p, p = 0..7
    const float* brow[8];
    #pragma unroll
    for (int p = 0; p < 8; p++)
        brow[p] = W + ((size_t)e * N + n0 + grpi + 32 * p) * K;

    auto load_stage = [&](int s) {
        const int kb = s * BK;
        const uint32_t sb = BUF + (uint32_t)(s & 3) * STG;
        #pragma unroll
        for (int p = 0; p < 4; p++)
            cpa16(sb + (uint32_t)((grpi + 32 * p) * 128) + pchunk, arow[p] + kb + csrc);
        #pragma unroll
        for (int p = 0; p < 8; p++)
            cpa16(sb + 16384u + (uint32_t)((grpi + 32 * p) * 128) + pchunk, brow[p] + kb + csrc);
        cpa_commit();
    };

    // -------- ldsm per-lane constants --------
    // A matrices: {rows0-7 lo, rows8-15 lo, rows0-7 hi, rows8-15 hi}
    const uint32_t arl  = (uint32_t)((lane & 7) + ((lane >> 3) & 1) * 8);
    const uint32_t asel = (uint32_t)(lane >> 4);
    // B matrices: {n0-7 lo, n0-7 hi, n8-15 lo, n8-15 hi}
    const uint32_t brl  = (uint32_t)((lane & 7) + (lane >> 4) * 8);
    const uint32_t bsel = (uint32_t)((lane >> 3) & 1);
    const uint32_t lx   = (uint32_t)(lane & 7);

    float acc[4][8][4];
    #pragma unroll
    for (int i = 0; i < 4; i++)
        #pragma unroll
        for (int j = 0; j < 8; j++)
            #pragma unroll
            for (int q = 0; q < 4; q++) acc[i][j][q] = 0.f;

    load_stage(0);
    load_stage(1);
    load_stage(2);

    for (int s = 0; s < S; s++) {
        cpa_wait<2>();
        __syncthreads();
        if (s + 3 < S) load_stage(s + 3);
        else cpa_commit();              // keep group count uniform for wait<2>

        const uint32_t sb = BUF + (uint32_t)(s & 3) * STG;
        const uint32_t aB = sb + (uint32_t)(wm * 64) * 128 + arl * 128;
        const uint32_t bB = sb + 16384u + (uint32_t)(wn * 64) * 128 + brl * 128;

        #pragma unroll
        for (uint32_t kk = 0; kk < 4; kk++) {
            const uint32_t ac = ((2 * kk + asel) ^ lx) << 4;
            const uint32_t bc = ((2 * kk + bsel) ^ lx) << 4;
            uint32_t a[4][4], b[4][4];
            #pragma unroll
            for (int mt = 0; mt < 4; mt++) {
                ldsm4(a[mt], aB + (uint32_t)(mt * 16 * 128) + ac);
                #pragma unroll
                for (int q = 0; q < 4; q++) a[mt][q] = f2tf32(a[mt][q]);
            }
            #pragma unroll
            for (int nb = 0; nb < 4; nb++) {
                ldsm4(b[nb], bB + (uint32_t)(nb * 16 * 128) + bc);
                #pragma unroll
                for (int q = 0; q < 4; q++) b[nb][q] = f2tf32(b[nb][q]);
            }
            #pragma unroll
            for (int mt = 0; mt < 4; mt++)
                #pragma unroll
                for (int nb = 0; nb < 4; nb++) {
                    mma_tf32(acc[mt][2 * nb],     a[mt], b[nb][0], b[nb][1]);
                    mma_tf32(acc[mt][2 * nb + 1], a[mt], b[nb][2], b[nb][3]);
                }
        }
    }

    // -------- epilogue --------
    const int grp = lane >> 2, qid = lane & 3;
    float bc2[8][2];
    #pragma unroll
    for (int nt = 0; nt < 8; nt++) {
        int col = n0 + wn * 64 + nt * 8 + qid * 2;
        bc2[nt][0] = __ldg(bias + e * N + col);
        bc2[nt][1] = __ldg(bias + e * N + col + 1);
    }
    #pragma unroll
    for (int mt = 0; mt < 4; mt++) {
        #pragma unroll
        for (int h = 0; h < 2; h++) {
            int r = m0 + wm * 64 + mt * 16 + grp + h * 8;
            if (r >= cnt) continue;
            #pragma unroll
            for (int nt = 0; nt < 8; nt++) {
                int col = n0 + wn * 64 + nt * 8 + qid * 2;
                float v0 = acc[mt][nt][h * 2 + 0] + bc2[nt][0];
                float v1 = acc[mt][nt][h * 2 + 1] + bc2[nt][1];
                if (PHASE == 1) {
                    v0 = 0.5f * v0 * (1.f + erff(v0 * 0.70710678118654752f));
                    v1 = 0.5f * v1 * (1.f + erff(v1 * 0.70710678118654752f));
                    float2 o = {v0, v1};
                    *(float2*)(g_H + ((size_t)e * NTOK + r) * DH + col) = o;
                } else {
                    float2 o = {v0, v1};
                    *(float2*)(g_Z + ((size_t)e * NTOK + r) * DM + col) = o;
                }
            }
        }
    }
}

// ------------------------- combine -------------------------------------------
__global__ void combine_kernel(const float* __restrict__ x,
                               const float* __restrict__ gamma,
                               const float* __restrict__ beta,
                               float* __restrict__ out) {
    const int t = blockIdx.x, tid = threadIdx.x;
    __shared__ float ssum[8], ssq[8];
    const float4 xv = *(const float4*)(x + (size_t)t * DM + tid * 4);
    float acc[4] = {0.f, 0.f, 0.f, 0.f};
    #pragma unroll
    for (int p = 0; p < 2; p++) {
        int e = g_eid[t * 2 + p], s = g_slot[t * 2 + p];
        float wgt = g_wt[t * 2 + p];
        const float4 zv = *(const float4*)(g_Z + ((size_t)e * NTOK + s) * DM + tid * 4);
        float z[4] = {xv.x + zv.x, xv.y + zv.y, xv.z + zv.z, xv.w + zv.w};
        float sum = 0.f, sq = 0.f;
        #pragma unroll
        for (int i = 0; i < 4; i++) { sum += z[i]; sq += z[i] * z[i]; }
        #pragma unroll
        for (int o = 16; o; o >>= 1) {
            sum += __shfl_xor_sync(0xffffffffu, sum, o);
            sq  += __shfl_xor_sync(0xffffffffu, sq,  o);
        }
        int w = tid >> 5, lane = tid & 31;
        if (lane == 0) { ssum[w] = sum; ssq[w] = sq; }
        __syncthreads();
        float tsum = 0.f, tsq = 0.f;
        #pragma unroll
        for (int i = 0; i < 8; i++) { tsum += ssum[i]; tsq += ssq[i]; }
        __syncthreads();
        float mu = tsum * (1.f / DM);
        float var = tsq * (1.f / DM) - mu * mu;
        float rstd = rsqrtf(var + 1e-6f);
        const float4 gv = *(const float4*)(gamma + (size_t)e * DM + tid * 4);
        const float4 bv = *(const float4*)(beta  + (size_t)e * DM + tid * 4);
        const float g4[4] = {gv.x, gv.y, gv.z, gv.w};
        const float b4[4] = {bv.x, bv.y, bv.z, bv.w};
        #pragma unroll
        for (int i = 0; i < 4; i++)
            acc[i] += wgt * ((z[i] - mu) * rstd * g4[i] + b4[i]);
    }
    float4 o4 = {acc[0], acc[1], acc[2], acc[3]};
    *(float4*)(out + (size_t)t * DM + tid * 4) = o4;
}

// ------------------------- launch --------------------------------------------
extern "C" void kernel_launch(void* const* d_in, const int* in_sizes, int n_in,
                              void* d_out, int out_size) {
    const float* x     = (const float*)d_in[0];
    const float* gw    = (const float*)d_in[1];
    const float* w1    = (const float*)d_in[2];
    const float* b1    = (const float*)d_in[3];
    const float* w2    = (const float*)d_in[4];
    const float* b2    = (const float*)d_in[5];
    const float* gamma = (const float*)d_in[6];
    const float* beta  = (const float*)d_in[7];
    float* out = (float*)d_out;

    cudaFuncSetAttribute(gemm_tf32<1>, cudaFuncAttributeMaxDynamicSharedMemorySize, SMEM_TOTAL);
    cudaFuncSetAttribute(gemm_tf32<2>, cudaFuncAttributeMaxDynamicSharedMemorySize, SMEM_TOTAL);

    reset_kernel<<<1, 32>>>();
    gate_kernel<<<NTOK, 128>>>(x, gw);

    dim3 g1(DH / BN, NTOK / BM, NE);
    gemm_tf32<1><<<g1, 256, SMEM_TOTAL>>>(x, w1, b1);

    dim3 g2(DM / BN, NTOK / BM, NE);
    gemm_tf32<2><<<g2, 256, SMEM_TOTAL>>>(nullptr, w2, b2);

    combine_kernel<<<NTOK, 256>>>(x, gamma, beta, out);
}